// round 11
// baseline (speedup 1.0000x reference)
#include <cuda_runtime.h>
#include <cuda_fp16.h>
#include <cstdint>

#define N_NODES 100000
#define E_EDGES 3200000
#define F_INDIM 512
#define H_DIM   128
#define C_OUT   40

typedef unsigned long long ull;

// ---------------- device scratch ----------------
__device__ __align__(16) float   g_h[N_NODES * H_DIM];
__device__ __align__(16) __half2 g_tmph[N_NODES * 64];
__device__ __align__(16) float   g_wide[N_NODES * C_OUT];
__device__ float g_attn0[N_NODES];
__device__ float g_dinv[N_NODES];
__device__ int   g_counts[N_NODES];
__device__ int   g_offsets[N_NODES];
__device__ int   g_cursor[N_NODES];
__device__ int   g_csr_row[E_EDGES];
__device__ float g_csr_val[E_EDGES];
__device__ int   g_partials[32];
__device__ int   g_is64;
__device__ __align__(16) float g_W2p[H_DIM * 48];
__device__ __align__(16) float g_bias192[192];
__device__ __align__(16) float g_B1[F_INDIM * 192];   // plain [k][n] concat W1|Ww|Wa

// ---------------- dtype detect / edge prep ----------------
__global__ void k_detect(const unsigned* __restrict__ ei_raw) {
    if (threadIdx.x == 0) g_is64 = 1;
    __syncthreads();
    unsigned v = ei_raw[2 * (threadIdx.x * 997 + 1) + 1];
    if (v != 0) atomicAnd(&g_is64, 0);
}
__device__ __forceinline__ void load_edge(const void* ei, int e, int is64, int& row, int& col) {
    if (is64) {
        const long long* p = (const long long*)ei;
        row = (int)p[e]; col = (int)p[E_EDGES + e];
    } else {
        const int* p = (const int*)ei;
        row = p[e]; col = p[E_EDGES + e];
    }
}
__global__ void k_init() {
    int n = blockIdx.x * blockDim.x + threadIdx.x;
    if (n < N_NODES) { g_dinv[n] = 1.0f; g_counts[n] = 0; }
}
__global__ void k_edge_deg(const void* __restrict__ ei, const float* __restrict__ ew) {
    int e = blockIdx.x * blockDim.x + threadIdx.x;
    if (e >= E_EDGES) return;
    int row, col;
    load_edge(ei, e, g_is64, row, col);
    atomicAdd(&g_dinv[col], ew[e]);
    atomicAdd(&g_counts[col], 1);
}
__global__ void k_rsqrt() {
    int n = blockIdx.x * blockDim.x + threadIdx.x;
    if (n < N_NODES) g_dinv[n] = rsqrtf(g_dinv[n]);
}
__global__ void k_scan1() {
    int t = threadIdx.x;
    int base = blockIdx.x * 4096 + t * 16;
    int vals[16]; int tot = 0;
#pragma unroll
    for (int i = 0; i < 16; i++) {
        int idx = base + i;
        int v = (idx < N_NODES) ? g_counts[idx] : 0;
        vals[i] = v; tot += v;
    }
    int lane = t & 31, w = t >> 5;
    int inc = tot;
#pragma unroll
    for (int o = 1; o < 32; o <<= 1) {
        int x = __shfl_up_sync(0xffffffffu, inc, o);
        if (lane >= o) inc += x;
    }
    __shared__ int wsum[8], wexc[8];
    if (lane == 31) wsum[w] = inc;
    __syncthreads();
    if (t == 0) {
        int run = 0;
        for (int i = 0; i < 8; i++) { wexc[i] = run; run += wsum[i]; }
        g_partials[blockIdx.x] = run;
    }
    __syncthreads();
    int run = wexc[w] + inc - tot;
#pragma unroll
    for (int i = 0; i < 16; i++) {
        int idx = base + i;
        if (idx < N_NODES) g_offsets[idx] = run;
        run += vals[i];
    }
}
__global__ void k_scan2() {
    int run = 0;
    for (int b = 0; b < 25; b++) { int v = g_partials[b]; g_partials[b] = run; run += v; }
}
__global__ void k_scan3() {
    int idx = blockIdx.x * blockDim.x + threadIdx.x;
    if (idx < N_NODES) {
        int o = g_offsets[idx] + g_partials[idx / 4096];
        g_offsets[idx] = o;
        g_cursor[idx] = o;
    }
}
__global__ void k_place(const void* __restrict__ ei, const float* __restrict__ ew) {
    int e = blockIdx.x * blockDim.x + threadIdx.x;
    if (e >= E_EDGES) return;
    int row, col;
    load_edge(ei, e, g_is64, row, col);
    int p = atomicAdd(&g_cursor[col], 1);
    g_csr_row[p] = row;
    g_csr_val[p] = g_dinv[row] * ew[e] * g_dinv[col];
}

// ---------------- weight packing ----------------
__global__ void k_packB_l1(const float* __restrict__ W1, const float* __restrict__ Ww,
                           const float* __restrict__ Wa) {
    int idx = blockIdx.x * blockDim.x + threadIdx.x;
    if (idx >= F_INDIM * 192) return;
    int k = idx / 192, n = idx % 192;
    float v = 0.0f;
    if (n < 128) v = W1[k * 128 + n];
    else if (n < 168) v = Ww[k * 40 + (n - 128)];
    else if (n < 170) v = Wa[k * 2 + (n - 168)];
    g_B1[idx] = v;
}
__global__ void k_pack(const float* __restrict__ W2, const float* __restrict__ b1,
                       const float* __restrict__ bw, const float* __restrict__ ba) {
    int i = blockIdx.x * blockDim.x + threadIdx.x;
    if (i < H_DIM * 48) {
        int k = i / 48, c = i % 48;
        g_W2p[i] = (c < 40) ? W2[k * 40 + c] : 0.0f;
    }
    if (i < 192)
        g_bias192[i] = (i < 128) ? b1[i] : ((i < 168) ? bw[i - 128] : ((i < 170) ? ba[i - 168] : 0.0f));
}

// ---------------- FFMA2 GEMM: 8M x (NT/16)N, reg-double-buffered operands -----
// CTA: 128 M x NT N, 256 thr (tx 16 x ty 16). Thread: 8 M x NP2 col-pairs.
// SEG = NT/64 segments; pair p -> col = 64*(p/2) + 4tx + 2*(p%2).
// Manual software pipeline: kk+1 operands loaded into alternate register bank
// BEFORE kk's FFMA2 burst -> LDS latency fully hidden under 96 fma-issue cyc.
// EPI 0: fused layer1 (h relu <128, wide 128-167, attn 168).  EPI 1: conv->tmph.
#define FMA2(c, a, b) asm("fma.rn.f32x2 %0, %1, %2, %0;" : "+l"(c) : "l"(a), "l"(b))
#define AST 132   // ull stride per kk row of duplicated A

__device__ __forceinline__ ull dup_f32(float v) {
    uint32_t u = __float_as_uint(v);
    ull d;
    asm("mov.b64 %0, {%1, %1};" : "=l"(d) : "r"(u));
    return d;
}

template<int NT, int EPI, int KT>
__global__ __launch_bounds__(256, 1) void gemm_f2(
    const float* __restrict__ A, const float* __restrict__ B, int NTOT, int nbase)
{
    constexpr int SEG  = NT / 64;              // B LDS.128 per kk (3 or 2)
    constexpr int NP2  = 2 * SEG;              // col-pairs per thread (6 or 4)
    constexpr int BF4  = NT / 64;              // float4 B ldg per thread per chunk
    constexpr int ABUF = 16 * AST;             // ull per A buffer
    constexpr int BBUF = 16 * NT;              // floats per B buffer
    constexpr int CH   = KT / 16;
    extern __shared__ __align__(16) char smem[];
    ull* Asd = (ull*)smem;                               // [2][ABUF]
    float* Bsf = (float*)(smem + 2 * ABUF * 8);          // [2][BBUF]
    const int tid = threadIdx.x;
    const int tx = tid & 15, ty = tid >> 4;
    const int m0 = blockIdx.x * 128;

    ull acc[8][NP2];
#pragma unroll
    for (int mp = 0; mp < 8; mp++)
#pragma unroll
        for (int p = 0; p < NP2; p++) acc[mp][p] = 0ull;

    const int ra = tid >> 2, ca = (tid & 3) << 2;
    const float* pA0 = A + (size_t)(m0 + ra) * KT + ca;
    const float* pA1 = A + (size_t)(m0 + ra + 64) * KT + ca;
    const bool okA0 = (m0 + ra) < N_NODES;
    const bool okA1 = (m0 + ra + 64) < N_NODES;
    int bkk[BF4], bnn[BF4];
    const float* pB[BF4];
#pragma unroll
    for (int j = 0; j < BF4; j++) {
        int idx = j * 256 + tid;
        bkk[j] = idx / (NT / 4);
        bnn[j] = (idx % (NT / 4)) * 4;
        pB[j] = B + (size_t)bkk[j] * NTOT + nbase + bnn[j];
    }

    float4 pfA0, pfA1;
    float4 pfB[BF4];

    auto ldg = [&]() {
        pfA0 = okA0 ? *(const float4*)pA0 : make_float4(0.f, 0.f, 0.f, 0.f);
        pfA1 = okA1 ? *(const float4*)pA1 : make_float4(0.f, 0.f, 0.f, 0.f);
        pA0 += 16; pA1 += 16;
#pragma unroll
        for (int j = 0; j < BF4; j++) { pfB[j] = *(const float4*)pB[j]; pB[j] += 16 * NTOT; }
    };
    auto sts = [&](int buf) {
        ull* da = Asd + buf * ABUF;
        da[(ca + 0) * AST + ra] = dup_f32(pfA0.x);
        da[(ca + 1) * AST + ra] = dup_f32(pfA0.y);
        da[(ca + 2) * AST + ra] = dup_f32(pfA0.z);
        da[(ca + 3) * AST + ra] = dup_f32(pfA0.w);
        da[(ca + 0) * AST + ra + 64] = dup_f32(pfA1.x);
        da[(ca + 1) * AST + ra + 64] = dup_f32(pfA1.y);
        da[(ca + 2) * AST + ra + 64] = dup_f32(pfA1.z);
        da[(ca + 3) * AST + ra + 64] = dup_f32(pfA1.w);
        float* db = Bsf + buf * BBUF;
#pragma unroll
        for (int j = 0; j < BF4; j++) *(float4*)(db + bkk[j] * NT + bnn[j]) = pfB[j];
    };

    ldg(); sts(0);
    __syncthreads();

#pragma unroll 1
    for (int c = 0; c < CH; c++) {
        const int buf = c & 1;
        if (c + 1 < CH) ldg();
        const ull* Ab = Asd + buf * ABUF + ty * 8;
        const float* Bb = Bsf + buf * BBUF + 4 * tx;

        // manual reg double-buffer: bank kk&1 holds current, other gets kk+1
        ull av[2][8];
        ull bv[2][NP2];
        auto ldops = [&](int kk, int bank) {
#pragma unroll
            for (int q = 0; q < 4; q++) {
                ulonglong2 a2 = *(const ulonglong2*)(Ab + kk * AST + 2 * q);
                av[bank][2 * q] = a2.x; av[bank][2 * q + 1] = a2.y;
            }
#pragma unroll
            for (int s = 0; s < SEG; s++) {
                ulonglong2 b2 = *(const ulonglong2*)(Bb + kk * NT + 64 * s);
                bv[bank][2 * s] = b2.x; bv[bank][2 * s + 1] = b2.y;
            }
        };

        ldops(0, 0);
#pragma unroll
        for (int kk = 0; kk < 16; kk++) {
            const int cb = kk & 1;
            if (kk < 15) ldops(kk + 1, cb ^ 1);
#pragma unroll
            for (int p = 0; p < NP2; p++)
#pragma unroll
                for (int mp = 0; mp < 8; mp++) FMA2(acc[mp][p], av[cb][mp], bv[cb][p]);
        }
        if (c + 1 < CH) sts(buf ^ 1);
        __syncthreads();
    }

    // ---- epilogue: acc[mp][p] = row m0+ty*8+mp, col nbase + 64*(p/2)+4tx+2*(p%2)
#pragma unroll
    for (int mp = 0; mp < 8; mp++) {
        const int r = m0 + ty * 8 + mp;
        if (r >= N_NODES) continue;
#pragma unroll
        for (int p = 0; p < NP2; p++) {
            const int col = nbase + 64 * (p >> 1) + 4 * tx + 2 * (p & 1);
            uint2 u = *(uint2*)&acc[mp][p];
            float x = __uint_as_float(u.x), y = __uint_as_float(u.y);
            if (EPI == 0) {
                if (col >= 170) continue;
                float2 bb = *(const float2*)&g_bias192[col];
                x += bb.x; y += bb.y;
                if (col < 128)
                    *(float2*)&g_h[(size_t)r * 128 + col] =
                        make_float2(fmaxf(x, 0.0f), fmaxf(y, 0.0f));
                else if (col < 168)
                    *(float2*)&g_wide[(size_t)r * 40 + (col - 128)] = make_float2(x, y);
                else
                    g_attn0[r] = 1.0f / (1.0f + expf(y - x));
            } else {
                g_tmph[(size_t)r * 64 + (col >> 1)] = __floats2half2_rn(x, y);
            }
        }
    }
}

// ---------------- aggregation: warp/node, fp16 features ----------------
__global__ __launch_bounds__(256) void k_aggregate(const float* __restrict__ bias,
                                                   float* __restrict__ outH) {
    int n = (blockIdx.x * blockDim.x + threadIdx.x) >> 5;
    int lane = threadIdx.x & 31;
    if (n >= N_NODES) return;
    float di = g_dinv[n];
    float s = di * di;
    uint2 tr = ((const uint2*)(g_tmph + (size_t)n * 64))[lane];
    float2 f0 = __half22float2(*(__half2*)&tr.x);
    float2 f1 = __half22float2(*(__half2*)&tr.y);
    float4 acc = make_float4(f0.x * s, f0.y * s, f1.x * s, f1.y * s);
    int st = g_offsets[n];
    int en = st + g_counts[n];
    for (int p = st; p < en; p++) {
        int r = g_csr_row[p];
        float v = g_csr_val[p];
        uint2 t = ((const uint2*)(g_tmph + (size_t)r * 64))[lane];
        float2 a = __half22float2(*(__half2*)&t.x);
        float2 b = __half22float2(*(__half2*)&t.y);
        acc.x += v * a.x; acc.y += v * a.y; acc.z += v * b.x; acc.w += v * b.y;
    }
    float4 b = ((const float4*)bias)[lane];
    acc.x = fmaxf(acc.x + b.x, 0.0f);
    acc.y = fmaxf(acc.y + b.y, 0.0f);
    acc.z = fmaxf(acc.z + b.z, 0.0f);
    acc.w = fmaxf(acc.w + b.w, 0.0f);
    ((float4*)(outH + (size_t)n * 128))[lane] = acc;
}

// ---------------- final skinny GEMM ----------------
__global__ __launch_bounds__(256) void gemm_final(const float* __restrict__ A,
                                                  const float* __restrict__ b2,
                                                  float* __restrict__ out) {
    __shared__ float As[16][68];
    __shared__ float Bs[16][48];
    const int tid = threadIdx.x;
    const int tx = tid & 15, ty = tid >> 4;
    const int m0 = blockIdx.x * 64;
    float acc[4][3];
#pragma unroll
    for (int i = 0; i < 4; i++)
#pragma unroll
        for (int j = 0; j < 3; j++) acc[i][j] = 0.0f;
    const int ra = tid >> 2;
    const int ca = (tid & 3) << 2;
    for (int k0 = 0; k0 < H_DIM; k0 += 16) {
        {
            int m = m0 + ra;
            float4 v = make_float4(0.f, 0.f, 0.f, 0.f);
            if (m < N_NODES) v = *(const float4*)(A + (size_t)m * H_DIM + k0 + ca);
            As[ca + 0][ra] = v.x; As[ca + 1][ra] = v.y;
            As[ca + 2][ra] = v.z; As[ca + 3][ra] = v.w;
        }
        if (tid < 192) {
            int kk = tid / 12;
            int nn = (tid % 12) * 4;
            *(float4*)&Bs[kk][nn] = *(const float4*)(g_W2p + (size_t)(k0 + kk) * 48 + nn);
        }
        __syncthreads();
#pragma unroll
        for (int kk = 0; kk < 16; kk++) {
            float a[4], b[3];
#pragma unroll
            for (int i = 0; i < 4; i++) a[i] = As[kk][ty * 4 + i];
#pragma unroll
            for (int j = 0; j < 3; j++) b[j] = Bs[kk][tx * 3 + j];
#pragma unroll
            for (int i = 0; i < 4; i++)
#pragma unroll
                for (int j = 0; j < 3; j++) acc[i][j] += a[i] * b[j];
        }
        __syncthreads();
    }
#pragma unroll
    for (int i = 0; i < 4; i++) {
        int m = m0 + ty * 4 + i;
        if (m >= N_NODES) continue;
        float a0 = g_attn0[m];
        float a1 = 1.0f - a0;
#pragma unroll
        for (int j = 0; j < 3; j++) {
            int c = tx * 3 + j;
            if (c < 40) {
                float deep = acc[i][j] + b2[c];
                out[(size_t)m * 40 + c] = deep * a0 + g_wide[(size_t)m * 40 + c] * a1;
            }
        }
    }
}

// ---------------- launch ----------------
extern "C" void kernel_launch(void* const* d_in, const int* in_sizes, int n_in,
                              void* d_out, int out_size)
{
    const float* x   = (const float*)d_in[0];
    const void*  ei  = d_in[1];
    const float* ew  = (const float*)d_in[2];
    const float* W1  = (const float*)d_in[3];
    const float* b1  = (const float*)d_in[4];
    const float* Wc1 = (const float*)d_in[5];
    const float* bc1 = (const float*)d_in[6];
    const float* Wc2 = (const float*)d_in[7];
    const float* bc2 = (const float*)d_in[8];
    const float* W2  = (const float*)d_in[9];
    const float* b2  = (const float*)d_in[10];
    const float* Ww  = (const float*)d_in[11];
    const float* bw  = (const float*)d_in[12];
    const float* Wa  = (const float*)d_in[13];
    const float* ba  = (const float*)d_in[14];
    float* out = (float*)d_out;

    float *h, *B1;
    cudaGetSymbolAddress((void**)&h,  g_h);
    cudaGetSymbolAddress((void**)&B1, g_B1);

    const int SM_192 = 2 * 16 * AST * 8 + 2 * 16 * 192 * 4;  // 58368
    const int SM_128 = 2 * 16 * AST * 8 + 2 * 16 * 128 * 4;  // 50176
    cudaFuncSetAttribute(gemm_f2<192, 0, F_INDIM>,
                         cudaFuncAttributeMaxDynamicSharedMemorySize, SM_192);
    cudaFuncSetAttribute(gemm_f2<128, 1, H_DIM>,
                         cudaFuncAttributeMaxDynamicSharedMemorySize, SM_128);

    const int EB = (E_EDGES + 255) / 256;
    const int NB = (N_NODES + 255) / 256;
    const int GB = (N_NODES + 127) / 128;      // 782

    // launch idx 3 = fused layer-1 GEMM (ncu capture slot)
    k_detect<<<1, 64>>>((const unsigned*)ei);
    k_pack<<<(H_DIM * 48 + 255) / 256, 256>>>(W2, b1, bw, ba);
    k_packB_l1<<<(F_INDIM * 192 + 255) / 256, 256>>>(W1, Ww, Wa);
    gemm_f2<192, 0, F_INDIM><<<GB, 256, SM_192>>>(x, B1, 192, 0);   // idx 3

    k_init<<<NB, 256>>>();
    k_edge_deg<<<EB, 256>>>(ei, ew);
    k_rsqrt<<<NB, 256>>>();
    k_scan1<<<25, 256>>>();
    k_scan2<<<1, 1>>>();
    k_scan3<<<NB, 256>>>();
    k_place<<<EB, 256>>>(ei, ew);

    gemm_f2<128, 1, H_DIM><<<GB, 256, SM_128>>>(h, Wc1, H_DIM, 0);
    k_aggregate<<<(N_NODES * 32 + 255) / 256, 256>>>(bc1, h);

    gemm_f2<128, 1, H_DIM><<<GB, 256, SM_128>>>(h, Wc2, H_DIM, 0);
    k_aggregate<<<(N_NODES * 32 + 255) / 256, 256>>>(bc2, h);

    gemm_final<<<(N_NODES + 63) / 64, 256>>>(h, b2, out);
}

// round 12
// speedup vs baseline: 1.0217x; 1.0217x over previous
#include <cuda_runtime.h>
#include <cuda_fp16.h>
#include <cstdint>

#define N_NODES 100000
#define E_EDGES 3200000
#define F_INDIM 512
#define H_DIM   128
#define C_OUT   40

typedef unsigned long long ull;

// ---------------- device scratch ----------------
__device__ __align__(16) float   g_h[N_NODES * H_DIM];
__device__ __align__(16) __half2 g_tmph[N_NODES * 64];
__device__ __align__(16) float   g_wide[N_NODES * C_OUT];
__device__ float g_attn0[N_NODES];
__device__ float g_dinv[N_NODES];
__device__ int   g_counts[N_NODES];
__device__ int   g_offsets[N_NODES];
__device__ int   g_cursor[N_NODES];
__device__ int   g_csr_row[E_EDGES];
__device__ float g_csr_val[E_EDGES];
__device__ int   g_partials[32];
__device__ int   g_is64;
__device__ __align__(16) float g_W2p[H_DIM * 48];
__device__ __align__(16) float g_bias192[192];
__device__ __align__(16) float g_B1[F_INDIM * 192];   // plain [k][n] concat W1|Ww|Wa

// ---------------- dtype detect / edge prep ----------------
__global__ void k_detect(const unsigned* __restrict__ ei_raw) {
    if (threadIdx.x == 0) g_is64 = 1;
    __syncthreads();
    unsigned v = ei_raw[2 * (threadIdx.x * 997 + 1) + 1];
    if (v != 0) atomicAnd(&g_is64, 0);
}
__device__ __forceinline__ void load_edge(const void* ei, int e, int is64, int& row, int& col) {
    if (is64) {
        const long long* p = (const long long*)ei;
        row = (int)p[e]; col = (int)p[E_EDGES + e];
    } else {
        const int* p = (const int*)ei;
        row = p[e]; col = p[E_EDGES + e];
    }
}
__global__ void k_init() {
    int n = blockIdx.x * blockDim.x + threadIdx.x;
    if (n < N_NODES) { g_dinv[n] = 1.0f; g_counts[n] = 0; }
}
__global__ void k_edge_deg(const void* __restrict__ ei, const float* __restrict__ ew) {
    int e = blockIdx.x * blockDim.x + threadIdx.x;
    if (e >= E_EDGES) return;
    int row, col;
    load_edge(ei, e, g_is64, row, col);
    atomicAdd(&g_dinv[col], ew[e]);
    atomicAdd(&g_counts[col], 1);
}
__global__ void k_rsqrt() {
    int n = blockIdx.x * blockDim.x + threadIdx.x;
    if (n < N_NODES) g_dinv[n] = rsqrtf(g_dinv[n]);
}
__global__ void k_scan1() {
    int t = threadIdx.x;
    int base = blockIdx.x * 4096 + t * 16;
    int vals[16]; int tot = 0;
#pragma unroll
    for (int i = 0; i < 16; i++) {
        int idx = base + i;
        int v = (idx < N_NODES) ? g_counts[idx] : 0;
        vals[i] = v; tot += v;
    }
    int lane = t & 31, w = t >> 5;
    int inc = tot;
#pragma unroll
    for (int o = 1; o < 32; o <<= 1) {
        int x = __shfl_up_sync(0xffffffffu, inc, o);
        if (lane >= o) inc += x;
    }
    __shared__ int wsum[8], wexc[8];
    if (lane == 31) wsum[w] = inc;
    __syncthreads();
    if (t == 0) {
        int run = 0;
        for (int i = 0; i < 8; i++) { wexc[i] = run; run += wsum[i]; }
        g_partials[blockIdx.x] = run;
    }
    __syncthreads();
    int run = wexc[w] + inc - tot;
#pragma unroll
    for (int i = 0; i < 16; i++) {
        int idx = base + i;
        if (idx < N_NODES) g_offsets[idx] = run;
        run += vals[i];
    }
}
__global__ void k_scan2() {
    int run = 0;
    for (int b = 0; b < 25; b++) { int v = g_partials[b]; g_partials[b] = run; run += v; }
}
__global__ void k_scan3() {
    int idx = blockIdx.x * blockDim.x + threadIdx.x;
    if (idx < N_NODES) {
        int o = g_offsets[idx] + g_partials[idx / 4096];
        g_offsets[idx] = o;
        g_cursor[idx] = o;
    }
}
__global__ void k_place(const void* __restrict__ ei, const float* __restrict__ ew) {
    int e = blockIdx.x * blockDim.x + threadIdx.x;
    if (e >= E_EDGES) return;
    int row, col;
    load_edge(ei, e, g_is64, row, col);
    int p = atomicAdd(&g_cursor[col], 1);
    g_csr_row[p] = row;
    g_csr_val[p] = g_dinv[row] * ew[e] * g_dinv[col];
}

// ---------------- weight packing ----------------
__global__ void k_packB_l1(const float* __restrict__ W1, const float* __restrict__ Ww,
                           const float* __restrict__ Wa) {
    int idx = blockIdx.x * blockDim.x + threadIdx.x;
    if (idx >= F_INDIM * 192) return;
    int k = idx / 192, n = idx % 192;
    float v = 0.0f;
    if (n < 128) v = W1[k * 128 + n];
    else if (n < 168) v = Ww[k * 40 + (n - 128)];
    else if (n < 170) v = Wa[k * 2 + (n - 168)];
    g_B1[idx] = v;
}
__global__ void k_pack(const float* __restrict__ W2, const float* __restrict__ b1,
                       const float* __restrict__ bw, const float* __restrict__ ba) {
    int i = blockIdx.x * blockDim.x + threadIdx.x;
    if (i < H_DIM * 48) {
        int k = i / 48, c = i % 48;
        g_W2p[i] = (c < 40) ? W2[k * 40 + c] : 0.0f;
    }
    if (i < 192)
        g_bias192[i] = (i < 128) ? b1[i] : ((i < 168) ? bw[i - 128] : ((i < 170) ? ba[i - 168] : 0.0f));
}

// ---------------- FFMA2 GEMM: 8M x (NT/16)N thread tile (at SIMT fp32 roofline)
#define FMA2(c, a, b) asm("fma.rn.f32x2 %0, %1, %2, %0;" : "+l"(c) : "l"(a), "l"(b))
#define AST 132

__device__ __forceinline__ ull dup_f32(float v) {
    uint32_t u = __float_as_uint(v);
    ull d;
    asm("mov.b64 %0, {%1, %1};" : "=l"(d) : "r"(u));
    return d;
}

template<int NT, int EPI, int KT>
__global__ __launch_bounds__(256, 1) void gemm_f2(
    const float* __restrict__ A, const float* __restrict__ B, int NTOT, int nbase)
{
    constexpr int SEG  = NT / 64;
    constexpr int NP2  = 2 * SEG;
    constexpr int BF4  = NT / 64;
    constexpr int ABUF = 16 * AST;
    constexpr int BBUF = 16 * NT;
    constexpr int CH   = KT / 16;
    extern __shared__ __align__(16) char smem[];
    ull* Asd = (ull*)smem;
    float* Bsf = (float*)(smem + 2 * ABUF * 8);
    const int tid = threadIdx.x;
    const int tx = tid & 15, ty = tid >> 4;
    const int m0 = blockIdx.x * 128;

    ull acc[8][NP2];
#pragma unroll
    for (int mp = 0; mp < 8; mp++)
#pragma unroll
        for (int p = 0; p < NP2; p++) acc[mp][p] = 0ull;

    const int ra = tid >> 2, ca = (tid & 3) << 2;
    const float* pA0 = A + (size_t)(m0 + ra) * KT + ca;
    const float* pA1 = A + (size_t)(m0 + ra + 64) * KT + ca;
    const bool okA0 = (m0 + ra) < N_NODES;
    const bool okA1 = (m0 + ra + 64) < N_NODES;
    int bkk[BF4], bnn[BF4];
    const float* pB[BF4];
#pragma unroll
    for (int j = 0; j < BF4; j++) {
        int idx = j * 256 + tid;
        bkk[j] = idx / (NT / 4);
        bnn[j] = (idx % (NT / 4)) * 4;
        pB[j] = B + (size_t)bkk[j] * NTOT + nbase + bnn[j];
    }

    float4 pfA0, pfA1;
    float4 pfB[BF4];

    auto ldg = [&]() {
        pfA0 = okA0 ? *(const float4*)pA0 : make_float4(0.f, 0.f, 0.f, 0.f);
        pfA1 = okA1 ? *(const float4*)pA1 : make_float4(0.f, 0.f, 0.f, 0.f);
        pA0 += 16; pA1 += 16;
#pragma unroll
        for (int j = 0; j < BF4; j++) { pfB[j] = *(const float4*)pB[j]; pB[j] += 16 * NTOT; }
    };
    auto sts = [&](int buf) {
        ull* da = Asd + buf * ABUF;
        da[(ca + 0) * AST + ra] = dup_f32(pfA0.x);
        da[(ca + 1) * AST + ra] = dup_f32(pfA0.y);
        da[(ca + 2) * AST + ra] = dup_f32(pfA0.z);
        da[(ca + 3) * AST + ra] = dup_f32(pfA0.w);
        da[(ca + 0) * AST + ra + 64] = dup_f32(pfA1.x);
        da[(ca + 1) * AST + ra + 64] = dup_f32(pfA1.y);
        da[(ca + 2) * AST + ra + 64] = dup_f32(pfA1.z);
        da[(ca + 3) * AST + ra + 64] = dup_f32(pfA1.w);
        float* db = Bsf + buf * BBUF;
#pragma unroll
        for (int j = 0; j < BF4; j++) *(float4*)(db + bkk[j] * NT + bnn[j]) = pfB[j];
    };

    ldg(); sts(0);
    __syncthreads();

#pragma unroll 1
    for (int c = 0; c < CH; c++) {
        const int buf = c & 1;
        if (c + 1 < CH) ldg();
        const ull* Ab = Asd + buf * ABUF + ty * 8;
        const float* Bb = Bsf + buf * BBUF + 4 * tx;
#pragma unroll
        for (int kk = 0; kk < 16; kk++) {
            ull av[8];
#pragma unroll
            for (int q = 0; q < 4; q++) {
                ulonglong2 a2 = *(const ulonglong2*)(Ab + kk * AST + 2 * q);
                av[2 * q] = a2.x; av[2 * q + 1] = a2.y;
            }
            ull bv[NP2];
#pragma unroll
            for (int s = 0; s < SEG; s++) {
                ulonglong2 b2 = *(const ulonglong2*)(Bb + kk * NT + 64 * s);
                bv[2 * s] = b2.x; bv[2 * s + 1] = b2.y;
            }
#pragma unroll
            for (int p = 0; p < NP2; p++)
#pragma unroll
                for (int mp = 0; mp < 8; mp++) FMA2(acc[mp][p], av[mp], bv[p]);
        }
        if (c + 1 < CH) sts(buf ^ 1);
        __syncthreads();
    }

#pragma unroll
    for (int mp = 0; mp < 8; mp++) {
        const int r = m0 + ty * 8 + mp;
        if (r >= N_NODES) continue;
#pragma unroll
        for (int p = 0; p < NP2; p++) {
            const int col = nbase + 64 * (p >> 1) + 4 * tx + 2 * (p & 1);
            uint2 u = *(uint2*)&acc[mp][p];
            float x = __uint_as_float(u.x), y = __uint_as_float(u.y);
            if (EPI == 0) {
                if (col >= 170) continue;
                float2 bb = *(const float2*)&g_bias192[col];
                x += bb.x; y += bb.y;
                if (col < 128)
                    *(float2*)&g_h[(size_t)r * 128 + col] =
                        make_float2(fmaxf(x, 0.0f), fmaxf(y, 0.0f));
                else if (col < 168)
                    *(float2*)&g_wide[(size_t)r * 40 + (col - 128)] = make_float2(x, y);
                else
                    g_attn0[r] = 1.0f / (1.0f + expf(y - x));
            } else {
                g_tmph[(size_t)r * 64 + (col >> 1)] = __floats2half2_rn(x, y);
            }
        }
    }
}

// ---------------- aggregation: warp/node, fp16 features ----------------
__global__ __launch_bounds__(256) void k_aggregate(const float* __restrict__ bias,
                                                   float* __restrict__ outH) {
    int n = (blockIdx.x * blockDim.x + threadIdx.x) >> 5;
    int lane = threadIdx.x & 31;
    if (n >= N_NODES) return;
    float di = g_dinv[n];
    float s = di * di;
    uint2 tr = ((const uint2*)(g_tmph + (size_t)n * 64))[lane];
    float2 f0 = __half22float2(*(__half2*)&tr.x);
    float2 f1 = __half22float2(*(__half2*)&tr.y);
    float4 acc = make_float4(f0.x * s, f0.y * s, f1.x * s, f1.y * s);
    int st = g_offsets[n];
    int en = st + g_counts[n];
    for (int p = st; p < en; p++) {
        int r = g_csr_row[p];
        float v = g_csr_val[p];
        uint2 t = ((const uint2*)(g_tmph + (size_t)r * 64))[lane];
        float2 a = __half22float2(*(__half2*)&t.x);
        float2 b = __half22float2(*(__half2*)&t.y);
        acc.x += v * a.x; acc.y += v * a.y; acc.z += v * b.x; acc.w += v * b.y;
    }
    float4 b = ((const float4*)bias)[lane];
    acc.x = fmaxf(acc.x + b.x, 0.0f);
    acc.y = fmaxf(acc.y + b.y, 0.0f);
    acc.z = fmaxf(acc.z + b.z, 0.0f);
    acc.w = fmaxf(acc.w + b.w, 0.0f);
    ((float4*)(outH + (size_t)n * 128))[lane] = acc;
}

// ---------------- final skinny GEMM ----------------
__global__ __launch_bounds__(256) void gemm_final(const float* __restrict__ A,
                                                  const float* __restrict__ b2,
                                                  float* __restrict__ out) {
    __shared__ float As[16][68];
    __shared__ float Bs[16][48];
    const int tid = threadIdx.x;
    const int tx = tid & 15, ty = tid >> 4;
    const int m0 = blockIdx.x * 64;
    float acc[4][3];
#pragma unroll
    for (int i = 0; i < 4; i++)
#pragma unroll
        for (int j = 0; j < 3; j++) acc[i][j] = 0.0f;
    const int ra = tid >> 2;
    const int ca = (tid & 3) << 2;
    for (int k0 = 0; k0 < H_DIM; k0 += 16) {
        {
            int m = m0 + ra;
            float4 v = make_float4(0.f, 0.f, 0.f, 0.f);
            if (m < N_NODES) v = *(const float4*)(A + (size_t)m * H_DIM + k0 + ca);
            As[ca + 0][ra] = v.x; As[ca + 1][ra] = v.y;
            As[ca + 2][ra] = v.z; As[ca + 3][ra] = v.w;
        }
        if (tid < 192) {
            int kk = tid / 12;
            int nn = (tid % 12) * 4;
            *(float4*)&Bs[kk][nn] = *(const float4*)(g_W2p + (size_t)(k0 + kk) * 48 + nn);
        }
        __syncthreads();
#pragma unroll
        for (int kk = 0; kk < 16; kk++) {
            float a[4], b[3];
#pragma unroll
            for (int i = 0; i < 4; i++) a[i] = As[kk][ty * 4 + i];
#pragma unroll
            for (int j = 0; j < 3; j++) b[j] = Bs[kk][tx * 3 + j];
#pragma unroll
            for (int i = 0; i < 4; i++)
#pragma unroll
                for (int j = 0; j < 3; j++) acc[i][j] += a[i] * b[j];
        }
        __syncthreads();
    }
#pragma unroll
    for (int i = 0; i < 4; i++) {
        int m = m0 + ty * 4 + i;
        if (m >= N_NODES) continue;
        float a0 = g_attn0[m];
        float a1 = 1.0f - a0;
#pragma unroll
        for (int j = 0; j < 3; j++) {
            int c = tx * 3 + j;
            if (c < 40) {
                float deep = acc[i][j] + b2[c];
                out[(size_t)m * 40 + c] = deep * a0 + g_wide[(size_t)m * 40 + c] * a1;
            }
        }
    }
}

// ---------------- launch (two-stream overlap, capture-safe fork/join) ----------
extern "C" void kernel_launch(void* const* d_in, const int* in_sizes, int n_in,
                              void* d_out, int out_size)
{
    const float* x   = (const float*)d_in[0];
    const void*  ei  = d_in[1];
    const float* ew  = (const float*)d_in[2];
    const float* W1  = (const float*)d_in[3];
    const float* b1  = (const float*)d_in[4];
    const float* Wc1 = (const float*)d_in[5];
    const float* bc1 = (const float*)d_in[6];
    const float* Wc2 = (const float*)d_in[7];
    const float* bc2 = (const float*)d_in[8];
    const float* W2  = (const float*)d_in[9];
    const float* b2  = (const float*)d_in[10];
    const float* Ww  = (const float*)d_in[11];
    const float* bw  = (const float*)d_in[12];
    const float* Wa  = (const float*)d_in[13];
    const float* ba  = (const float*)d_in[14];
    float* out = (float*)d_out;

    float *h, *B1;
    cudaGetSymbolAddress((void**)&h,  g_h);
    cudaGetSymbolAddress((void**)&B1, g_B1);

    // streams/events created once, on the (uncaptured) correctness call
    static cudaStream_t s2 = nullptr;
    static cudaEvent_t evFork, evPrep, evWide;
    if (!s2) {
        cudaStreamCreateWithFlags(&s2, cudaStreamNonBlocking);
        cudaEventCreateWithFlags(&evFork, cudaEventDisableTiming);
        cudaEventCreateWithFlags(&evPrep, cudaEventDisableTiming);
        cudaEventCreateWithFlags(&evWide, cudaEventDisableTiming);
    }

    const int SM_128 = 2 * 16 * AST * 8 + 2 * 16 * 128 * 4;  // 50176
    const int SM_64  = 2 * 16 * AST * 8 + 2 * 16 * 64 * 4;   // 41984
    cudaFuncSetAttribute(gemm_f2<128, 0, F_INDIM>,
                         cudaFuncAttributeMaxDynamicSharedMemorySize, SM_128);
    cudaFuncSetAttribute(gemm_f2<64, 0, F_INDIM>,
                         cudaFuncAttributeMaxDynamicSharedMemorySize, SM_64);
    cudaFuncSetAttribute(gemm_f2<128, 1, H_DIM>,
                         cudaFuncAttributeMaxDynamicSharedMemorySize, SM_128);

    const int EB = (E_EDGES + 255) / 256;
    const int NB = (N_NODES + 255) / 256;
    const int GB = (N_NODES + 127) / 128;      // 782

    // ---- stream 0 (capture stream): packing, then fork ----
    k_detect<<<1, 64>>>((const unsigned*)ei);
    k_pack<<<(H_DIM * 48 + 255) / 256, 256>>>(W2, b1, bw, ba);
    k_packB_l1<<<(F_INDIM * 192 + 255) / 256, 256>>>(W1, Ww, Wa);
    cudaEventRecord(evFork, 0);

    // ---- side stream: edge prep (LSU-bound), then wide+attn gemm ----
    cudaStreamWaitEvent(s2, evFork, 0);
    k_init<<<NB, 256, 0, s2>>>();
    k_edge_deg<<<EB, 256, 0, s2>>>(ei, ew);
    k_rsqrt<<<NB, 256, 0, s2>>>();
    k_scan1<<<25, 256, 0, s2>>>();
    k_scan2<<<1, 1, 0, s2>>>();
    k_scan3<<<NB, 256, 0, s2>>>();
    k_place<<<EB, 256, 0, s2>>>(ei, ew);
    cudaEventRecord(evPrep, s2);
    gemm_f2<64, 0, F_INDIM><<<GB, 256, SM_64, s2>>>(x, B1, 192, 128);  // wide+attn
    cudaEventRecord(evWide, s2);

    // ---- main stream: deep chain ----
    gemm_f2<128, 0, F_INDIM><<<GB, 256, SM_128>>>(x, B1, 192, 0);      // h = relu(xW1+b1)
    gemm_f2<128, 1, H_DIM><<<GB, 256, SM_128>>>(h, Wc1, H_DIM, 0);     // conv1 gemm
    cudaStreamWaitEvent(0, evPrep, 0);
    k_aggregate<<<(N_NODES * 32 + 255) / 256, 256>>>(bc1, h);
    gemm_f2<128, 1, H_DIM><<<GB, 256, SM_128>>>(h, Wc2, H_DIM, 0);     // conv2 gemm
    k_aggregate<<<(N_NODES * 32 + 255) / 256, 256>>>(bc2, h);
    cudaStreamWaitEvent(0, evWide, 0);
    gemm_final<<<(N_NODES + 63) / 64, 256>>>(h, b2, out);
}